// round 1
// baseline (speedup 1.0000x reference)
#include <cuda_runtime.h>
#include <math.h>

// Problem constants
#define NROWS 100000
#define DDIM  512
#define KCOMP 32
#define H1DIM 512
#define H2DIM 256

// ---------------------------------------------------------------------------
// Device scratch (no cudaMalloc allowed)
// ---------------------------------------------------------------------------
__device__ float  g_h1[(long long)NROWS * H1DIM];   // 204.8 MB
__device__ float  g_h2[(long long)NROWS * H2DIM];   // 102.4 MB
__device__ float  g_att[(long long)NROWS * KCOMP];  // 12.8 MB
__device__ float  g_S0[KCOMP];
__device__ float  g_S1[KCOMP * DDIM];
__device__ float  g_S2[KCOMP * DDIM];
__device__ float2 g_pivmiv[DDIM * KCOMP];           // (inv_var, mean*inv_var), [d][k]
__device__ float  g_Ck[KCOMP];

// ---------------------------------------------------------------------------
// Zero accumulators (must run every replay)
// ---------------------------------------------------------------------------
__global__ void zero_kernel() {
    int i = blockIdx.x * blockDim.x + threadIdx.x;
    if (i < KCOMP) g_S0[i] = 0.f;
    if (i < KCOMP * DDIM) { g_S1[i] = 0.f; g_S2[i] = 0.f; }
}

// ---------------------------------------------------------------------------
// Tiled fp32 GEMM + bias + softplus:  C[M,Nd] = softplus(A[M,K] @ B[K,Nd] + b)
// BM=64, BN=64, BK=16, 256 threads, 4x4 microtile
// ---------------------------------------------------------------------------
__device__ __forceinline__ float softplusf(float v) {
    return fmaxf(v, 0.f) + log1pf(expf(-fabsf(v)));
}

__global__ void __launch_bounds__(256)
gemm_bias_softplus(const float* __restrict__ A, const float* __restrict__ B,
                   const float* __restrict__ bias, float* __restrict__ C,
                   int M, int K, int Nd)
{
    __shared__ float As[16][68];   // transposed A tile, 272B row stride (16B-aligned)
    __shared__ float Bs[16][64];

    const int tid = threadIdx.x;
    const int m0 = blockIdx.x * 64;
    const int n0 = blockIdx.y * 64;
    const int tx = tid & 15;
    const int ty = tid >> 4;

    const int arow = tid >> 2;          // 0..63
    const int ak4  = (tid & 3) * 4;     // 0,4,8,12
    const int brow = tid >> 4;          // 0..15
    const int bc4  = (tid & 15) * 4;    // 0..60

    float acc[4][4];
#pragma unroll
    for (int i = 0; i < 4; i++)
#pragma unroll
        for (int j = 0; j < 4; j++) acc[i][j] = 0.f;

    for (int k0 = 0; k0 < K; k0 += 16) {
        float4 a4;
        int gr = m0 + arow;
        if (gr < M) a4 = *(const float4*)(A + (size_t)gr * K + k0 + ak4);
        else        a4 = make_float4(0.f, 0.f, 0.f, 0.f);
        As[ak4 + 0][arow] = a4.x;
        As[ak4 + 1][arow] = a4.y;
        As[ak4 + 2][arow] = a4.z;
        As[ak4 + 3][arow] = a4.w;

        float4 b4 = *(const float4*)(B + (size_t)(k0 + brow) * Nd + n0 + bc4);
        *(float4*)&Bs[brow][bc4] = b4;

        __syncthreads();

#pragma unroll
        for (int kk = 0; kk < 16; kk++) {
            float4 av = *(const float4*)(&As[kk][ty * 4]);
            float4 bv = *(const float4*)(&Bs[kk][tx * 4]);
            float a[4] = {av.x, av.y, av.z, av.w};
            float b[4] = {bv.x, bv.y, bv.z, bv.w};
#pragma unroll
            for (int i = 0; i < 4; i++)
#pragma unroll
                for (int j = 0; j < 4; j++)
                    acc[i][j] = fmaf(a[i], b[j], acc[i][j]);
        }
        __syncthreads();
    }

    float bb[4];
#pragma unroll
    for (int j = 0; j < 4; j++) bb[j] = bias[n0 + tx * 4 + j];

#pragma unroll
    for (int i = 0; i < 4; i++) {
        int r = m0 + ty * 4 + i;
        if (r < M) {
            float4 o;
            o.x = softplusf(acc[i][0] + bb[0]);
            o.y = softplusf(acc[i][1] + bb[1]);
            o.z = softplusf(acc[i][2] + bb[2]);
            o.w = softplusf(acc[i][3] + bb[3]);
            *(float4*)(C + (size_t)r * Nd + n0 + tx * 4) = o;
        }
    }
}

// ---------------------------------------------------------------------------
// att = softmax(h2 @ W3 + b3), also accumulates att_sum into g_S0
// 256 threads = 8 warps, one row per warp, W3 cached in smem
// ---------------------------------------------------------------------------
__global__ void __launch_bounds__(256)
attn_softmax_kernel(const float* __restrict__ W3, const float* __restrict__ b3)
{
    __shared__ float sW[H2DIM * KCOMP];   // 32 KB
    __shared__ float sh[8][H2DIM];        // 8 KB
    __shared__ float ssum[KCOMP];

    const int tid  = threadIdx.x;
    const int wid  = tid >> 5;
    const int lane = tid & 31;

    for (int i = tid; i < H2DIM * KCOMP; i += 256) sW[i] = W3[i];
    if (tid < KCOMP) ssum[tid] = 0.f;
    float bk = b3[lane];
    __syncthreads();

    for (int row = blockIdx.x * 8 + wid; row < NROWS; row += gridDim.x * 8) {
#pragma unroll
        for (int q = 0; q < 8; q++)
            sh[wid][lane + q * 32] = g_h2[(size_t)row * H2DIM + lane + q * 32];
        __syncwarp();

        float acc = bk;
#pragma unroll 8
        for (int j = 0; j < H2DIM; j++)
            acc = fmaf(sh[wid][j], sW[j * KCOMP + lane], acc);

        // warp softmax over K=32
        float m = acc;
#pragma unroll
        for (int o = 16; o > 0; o >>= 1) m = fmaxf(m, __shfl_xor_sync(0xffffffffu, m, o));
        float e = expf(acc - m);
        float s = e;
#pragma unroll
        for (int o = 16; o > 0; o >>= 1) s += __shfl_xor_sync(0xffffffffu, s, o);
        float p = e / s;

        g_att[(size_t)row * KCOMP + lane] = p;
        atomicAdd(&ssum[lane], p);
        __syncwarp();
    }

    __syncthreads();
    if (tid < KCOMP) atomicAdd(&g_S0[tid], ssum[tid]);
}

// ---------------------------------------------------------------------------
// Weighted stats: S1[k,d] = sum_n att[n,k]*x[n,d], S2 with x^2
// grid = (ceil(N/2048), 8 d-tiles), 128 threads: 64 d-lanes x 2 k-halves
// ---------------------------------------------------------------------------
#define STAT_ROWS 2048
__global__ void __launch_bounds__(128)
stats_kernel(const float* __restrict__ x)
{
    __shared__ float sa[32][32];

    const int tid = threadIdx.x;
    const int dl  = tid & 63;
    const int kh  = tid >> 6;
    const int d   = blockIdx.y * 64 + dl;
    const int n0  = blockIdx.x * STAT_ROWS;

    float s1[16], s2[16];
#pragma unroll
    for (int i = 0; i < 16; i++) { s1[i] = 0.f; s2[i] = 0.f; }

    for (int rb = 0; rb < STAT_ROWS; rb += 32) {
#pragma unroll
        for (int q = 0; q < 8; q++) {
            int idx = tid + q * 128;
            int r = n0 + rb + (idx >> 5);
            sa[idx >> 5][idx & 31] = (r < NROWS) ? g_att[(size_t)r * KCOMP + (idx & 31)] : 0.f;
        }
        __syncthreads();

#pragma unroll 4
        for (int rr = 0; rr < 32; rr++) {
            int row = n0 + rb + rr;
            float xv = (row < NROWS) ? x[(size_t)row * DDIM + d] : 0.f;
            float x2 = xv * xv;
            const float* ap = &sa[rr][kh * 16];
#pragma unroll
            for (int i = 0; i < 16; i++) {
                float a = ap[i];
                s1[i] = fmaf(a, xv, s1[i]);
                s2[i] = fmaf(a, x2, s2[i]);
            }
        }
        __syncthreads();
    }

#pragma unroll
    for (int i = 0; i < 16; i++) {
        int k = kh * 16 + i;
        atomicAdd(&g_S1[k * DDIM + d], s1[i]);
        atomicAdd(&g_S2[k * DDIM + d], s2[i]);
    }
}

// ---------------------------------------------------------------------------
// Finalize per-component params; write vars to output tail
// 32 blocks (one per k) x 256 threads
// ---------------------------------------------------------------------------
__global__ void __launch_bounds__(256)
finalize_kernel(float* __restrict__ out_vars)
{
    const int k = blockIdx.x;
    const int t = threadIdx.x;
    const float inv_s0 = 1.0f / g_S0[k];

    float csum = 0.f;
    for (int d = t; d < DDIM; d += 256) {
        float mean = g_S1[k * DDIM + d] * inv_s0;
        float ex2  = g_S2[k * DDIM + d] * inv_s0;
        float var  = ex2 - mean * mean;
        float iv   = 1.0f / var;
        float miv  = mean * iv;
        out_vars[k * DDIM + d] = var;
        g_pivmiv[d * KCOMP + k] = make_float2(iv, miv);
        csum += mean * miv + logf(var);
    }

    __shared__ float red[256];
    red[t] = csum;
    __syncthreads();
    if (t < 128) red[t] += red[t + 128];
    __syncthreads();
    if (t < 64) red[t] += red[t + 64];
    __syncthreads();
    if (t < 32) {
        float v = red[t] + red[t + 32];
#pragma unroll
        for (int o = 16; o > 0; o >>= 1) v += __shfl_xor_sync(0xffffffffu, v, o);
        if (t == 0)
            g_Ck[k] = -0.5f * v - (float)DDIM * 0.9189385332046727f;
    }
}

// ---------------------------------------------------------------------------
// Final GMM log-likelihood: out[n,k] = sum_d xv*(miv - 0.5*xv*iv) + Ck
// 128 threads = 4 warps; each warp owns 16 rows; lane = k; iv/miv in regs.
// ---------------------------------------------------------------------------
template <bool GUARD>
__device__ __forceinline__ void gmm_out_body(const float* __restrict__ x,
                                             float* __restrict__ out,
                                             int base, int lane, float ck)
{
    float acc[16];
#pragma unroll
    for (int r = 0; r < 16; r++) acc[r] = 0.f;

    for (int c = 0; c < 16; c++) {
        float2 pm[32];
#pragma unroll
        for (int j = 0; j < 32; j++)
            pm[j] = g_pivmiv[(c * 32 + j) * KCOMP + lane];

#pragma unroll
        for (int r = 0; r < 16; r++) {
            if (GUARD && (base + r >= NROWS)) continue;
            const float4* xp = (const float4*)(x + (size_t)(base + r) * DDIM + c * 32);
#pragma unroll
            for (int q = 0; q < 8; q++) {
                float4 xq = xp[q];
                {
                    float xv = xq.x, xh = -0.5f * xv;
                    float t = fmaf(xh, pm[q * 4 + 0].x, pm[q * 4 + 0].y);
                    acc[r] = fmaf(xv, t, acc[r]);
                }
                {
                    float xv = xq.y, xh = -0.5f * xv;
                    float t = fmaf(xh, pm[q * 4 + 1].x, pm[q * 4 + 1].y);
                    acc[r] = fmaf(xv, t, acc[r]);
                }
                {
                    float xv = xq.z, xh = -0.5f * xv;
                    float t = fmaf(xh, pm[q * 4 + 2].x, pm[q * 4 + 2].y);
                    acc[r] = fmaf(xv, t, acc[r]);
                }
                {
                    float xv = xq.w, xh = -0.5f * xv;
                    float t = fmaf(xh, pm[q * 4 + 3].x, pm[q * 4 + 3].y);
                    acc[r] = fmaf(xv, t, acc[r]);
                }
            }
        }
    }

#pragma unroll
    for (int r = 0; r < 16; r++) {
        int row = base + r;
        if (!GUARD || row < NROWS)
            out[(size_t)row * KCOMP + lane] = acc[r] + ck;
    }
}

__global__ void __launch_bounds__(128)
gmm_out_kernel(const float* __restrict__ x, float* __restrict__ out)
{
    const int lane = threadIdx.x & 31;
    const int w = blockIdx.x * 4 + (threadIdx.x >> 5);
    const int base = w * 16;
    if (base >= NROWS) return;
    const float ck = g_Ck[lane];

    if (base + 16 <= NROWS)
        gmm_out_body<false>(x, out, base, lane, ck);
    else
        gmm_out_body<true>(x, out, base, lane, ck);
}

// ---------------------------------------------------------------------------
// Launch
// ---------------------------------------------------------------------------
extern "C" void kernel_launch(void* const* d_in, const int* in_sizes, int n_in,
                              void* d_out, int out_size)
{
    const float* x  = (const float*)d_in[0];
    const float* W1 = (const float*)d_in[1];
    const float* b1 = (const float*)d_in[2];
    const float* W2 = (const float*)d_in[3];
    const float* b2 = (const float*)d_in[4];
    const float* W3 = (const float*)d_in[5];
    const float* b3 = (const float*)d_in[6];
    float* out = (float*)d_out;

    float *h1p = nullptr, *h2p = nullptr;
    cudaGetSymbolAddress((void**)&h1p, g_h1);
    cudaGetSymbolAddress((void**)&h2p, g_h2);

    // 0) zero accumulators
    zero_kernel<<<64, 256>>>();

    // 1) h1 = softplus(x @ W1 + b1)
    {
        dim3 grid((NROWS + 63) / 64, H1DIM / 64);
        gemm_bias_softplus<<<grid, 256>>>(x, W1, b1, h1p, NROWS, DDIM, H1DIM);
    }

    // 2) h2 = softplus(h1 @ W2 + b2)
    {
        dim3 grid((NROWS + 63) / 64, H2DIM / 64);
        gemm_bias_softplus<<<grid, 256>>>(h1p, W2, b2, h2p, NROWS, H1DIM, H2DIM);
    }

    // 3) att = softmax(h2 @ W3 + b3) + att_sum accumulation
    attn_softmax_kernel<<<1250, 256>>>(W3, b3);

    // 4) weighted stats S1, S2
    {
        dim3 grid((NROWS + STAT_ROWS - 1) / STAT_ROWS, DDIM / 64);
        stats_kernel<<<grid, 128>>>(x);
    }

    // 5) finalize params + write vars output
    finalize_kernel<<<KCOMP, 256>>>(out + (size_t)NROWS * KCOMP);

    // 6) GMM log-likelihood output
    {
        int nblocks = (NROWS + 63) / 64;   // 4 warps x 16 rows per block
        gmm_out_kernel<<<nblocks, 128>>>(x, out);
    }
}

// round 3
// speedup vs baseline: 1.9375x; 1.9375x over previous
#include <cuda_runtime.h>
#include <math.h>
#include <stdint.h>

// Problem constants
#define NROWS 100000
#define DDIM  512
#define KCOMP 32
#define H1DIM 512
#define H2DIM 256

// ---------------------------------------------------------------------------
// Device scratch (no cudaMalloc allowed)
// ---------------------------------------------------------------------------
__device__ float  g_h1[(size_t)NROWS * H1DIM];   // 204.8 MB
__device__ float  g_h2[(size_t)NROWS * H2DIM];   // 102.4 MB
__device__ float  g_att[(size_t)NROWS * KCOMP];  // 12.8 MB
__device__ float  g_S0[KCOMP];
__device__ float  g_S1[KCOMP * DDIM];
__device__ float  g_S2[KCOMP * DDIM];
__device__ float2 g_pivmiv[DDIM * KCOMP];
__device__ float  g_Ck[KCOMP];
__device__ float  g_W1t[(size_t)H1DIM * DDIM];   // W1^T [n][k], tf32-rounded
__device__ float  g_W2t[(size_t)H2DIM * H1DIM];  // W2^T [n][k], tf32-rounded

__device__ __forceinline__ float softplusf(float v) {
    return fmaxf(v, 0.f) + log1pf(expf(-fabsf(v)));
}
__device__ __forceinline__ float to_tf32_rn(float v) {
    float o;
    asm("cvt.rna.tf32.f32 %0, %1;" : "=f"(o) : "f"(v));
    return o;
}

// ---------------------------------------------------------------------------
// Zero accumulators
// ---------------------------------------------------------------------------
__global__ void zero_kernel() {
    int i = blockIdx.x * blockDim.x + threadIdx.x;
    if (i < KCOMP) g_S0[i] = 0.f;
    if (i < KCOMP * DDIM) { g_S1[i] = 0.f; g_S2[i] = 0.f; }
}

// ---------------------------------------------------------------------------
// Transpose W [K][Nd] -> Wt [Nd][K], rounding to tf32 (RN)
// ---------------------------------------------------------------------------
__global__ void transpose_tf32(const float* __restrict__ W, float* __restrict__ Wt,
                               int K, int Nd)
{
    __shared__ float t[32][33];
    int n0 = blockIdx.x * 32, k0 = blockIdx.y * 32;
    int x = threadIdx.x, y = threadIdx.y;
    for (int i = y; i < 32; i += 8) {
        int k = k0 + i, n = n0 + x;
        t[i][x] = (k < K && n < Nd) ? W[(size_t)k * Nd + n] : 0.f;
    }
    __syncthreads();
    for (int i = y; i < 32; i += 8) {
        int n = n0 + i, k = k0 + x;
        if (n < Nd && k < K)
            Wt[(size_t)n * K + k] = to_tf32_rn(t[x][i]);
    }
}

// ---------------------------------------------------------------------------
// tf32 mma.sync GEMM + bias + softplus
//   C[M,Nd] = softplus(A[M,512] @ Bt[Nd,512]^T + bias)
// BM=128, BN=128, BK=32, 256 threads, 8 warps (4 along M x 2 along N),
// warp tile 32x64 via m16n8k8. Double-buffered smem, padded stride 36.
// ---------------------------------------------------------------------------
#define BM 128
#define BN 128
#define BK 32
#define KDIM 512
#define AST 36
#define STAGE_F (BM * AST)          // floats per A (or B) stage
#define GEMM_SMEM (4 * STAGE_F * 4) // bytes: 2 stages x (A+B)

__device__ __forceinline__ void mma_tf32(float* c, const uint32_t* a, const uint32_t* b) {
    asm volatile(
        "mma.sync.aligned.m16n8k8.row.col.f32.tf32.tf32.f32 "
        "{%0,%1,%2,%3}, {%4,%5,%6,%7}, {%8,%9}, {%0,%1,%2,%3};"
        : "+f"(c[0]), "+f"(c[1]), "+f"(c[2]), "+f"(c[3])
        : "r"(a[0]), "r"(a[1]), "r"(a[2]), "r"(a[3]), "r"(b[0]), "r"(b[1]));
}

__global__ void __launch_bounds__(256)
gemm_mma(const float* __restrict__ A, const float* __restrict__ Bt,
         const float* __restrict__ bias, float* __restrict__ C,
         int M, int Nd)
{
    extern __shared__ float sm[];
    float* Asm = sm;                  // [2][BM][AST]
    float* Bsm = sm + 2 * STAGE_F;    // [2][BN][AST]

    const int tid  = threadIdx.x;
    const int lane = tid & 31;
    const int warp = tid >> 5;
    const int wm   = warp >> 1;   // 0..3
    const int wn   = warp & 1;    // 0..1
    const int g    = lane >> 2;   // 0..7
    const int t    = lane & 3;    // 0..3

    const int m0 = blockIdx.x * BM;
    const int n0 = blockIdx.y * BN;

    float acc[2][8][4];
#pragma unroll
    for (int i = 0; i < 2; i++)
#pragma unroll
        for (int j = 0; j < 8; j++)
#pragma unroll
            for (int q = 0; q < 4; q++) acc[i][j][q] = 0.f;

    // load mapping: 1024 float4 per stage per matrix; thread handles 4 each
    const int lrow[4] = { tid >> 3, (tid + 256) >> 3, (tid + 512) >> 3, (tid + 768) >> 3 };
    const int lc4 = (tid & 7) * 4;

    // ---- prologue: stage 0 ----
#pragma unroll
    for (int q = 0; q < 4; q++) {
        int r = lrow[q];
        float4 a4 = (m0 + r < M) ? *(const float4*)(A + (size_t)(m0 + r) * KDIM + lc4)
                                 : make_float4(0.f, 0.f, 0.f, 0.f);
        float* d = Asm + r * AST + lc4;
        d[0] = to_tf32_rn(a4.x); d[1] = to_tf32_rn(a4.y);
        d[2] = to_tf32_rn(a4.z); d[3] = to_tf32_rn(a4.w);
        float4 b4 = *(const float4*)(Bt + (size_t)(n0 + r) * KDIM + lc4);
        *(float4*)(Bsm + r * AST + lc4) = b4;
    }
    __syncthreads();

    const int NCH = KDIM / BK;  // 16
    for (int c = 0; c < NCH; c++) {
        int s = c & 1;
        float4 pa[4], pb[4];
        if (c + 1 < NCH) {
            int k0 = (c + 1) * BK;
#pragma unroll
            for (int q = 0; q < 4; q++) {
                int r = lrow[q];
                pa[q] = (m0 + r < M) ? *(const float4*)(A + (size_t)(m0 + r) * KDIM + k0 + lc4)
                                     : make_float4(0.f, 0.f, 0.f, 0.f);
                pb[q] = *(const float4*)(Bt + (size_t)(n0 + r) * KDIM + k0 + lc4);
            }
        }

        const float* Ab = Asm + s * STAGE_F;
        const float* Bb = Bsm + s * STAGE_F;
#pragma unroll
        for (int ks = 0; ks < 4; ks++) {
            int k = ks * 8;
            uint32_t af[2][4], bf[8][2];
#pragma unroll
            for (int i = 0; i < 2; i++) {
                int r = wm * 32 + i * 16 + g;
                af[i][0] = __float_as_uint(Ab[r * AST + k + t]);
                af[i][1] = __float_as_uint(Ab[(r + 8) * AST + k + t]);
                af[i][2] = __float_as_uint(Ab[r * AST + k + t + 4]);
                af[i][3] = __float_as_uint(Ab[(r + 8) * AST + k + t + 4]);
            }
#pragma unroll
            for (int j = 0; j < 8; j++) {
                int n = wn * 64 + j * 8 + g;
                bf[j][0] = __float_as_uint(Bb[n * AST + k + t]);
                bf[j][1] = __float_as_uint(Bb[n * AST + k + t + 4]);
            }
#pragma unroll
            for (int i = 0; i < 2; i++)
#pragma unroll
                for (int j = 0; j < 8; j++)
                    mma_tf32(acc[i][j], af[i], bf[j]);
        }

        if (c + 1 < NCH) {
            float* Ad = Asm + (s ^ 1) * STAGE_F;
            float* Bd = Bsm + (s ^ 1) * STAGE_F;
#pragma unroll
            for (int q = 0; q < 4; q++) {
                int r = lrow[q];
                float* d = Ad + r * AST + lc4;
                d[0] = to_tf32_rn(pa[q].x); d[1] = to_tf32_rn(pa[q].y);
                d[2] = to_tf32_rn(pa[q].z); d[3] = to_tf32_rn(pa[q].w);
                *(float4*)(Bd + r * AST + lc4) = pb[q];
            }
            __syncthreads();
        }
    }

    // ---- epilogue: bias + softplus ----
#pragma unroll
    for (int i = 0; i < 2; i++) {
        int r = m0 + wm * 32 + i * 16 + g;
#pragma unroll
        for (int j = 0; j < 8; j++) {
            int col = n0 + wn * 64 + j * 8 + 2 * t;
            float bb0 = __ldg(bias + col), bb1 = __ldg(bias + col + 1);
            if (r < M) {
                float2 o;
                o.x = softplusf(acc[i][j][0] + bb0);
                o.y = softplusf(acc[i][j][1] + bb1);
                *(float2*)(C + (size_t)r * Nd + col) = o;
            }
            if (r + 8 < M) {
                float2 o;
                o.x = softplusf(acc[i][j][2] + bb0);
                o.y = softplusf(acc[i][j][3] + bb1);
                *(float2*)(C + (size_t)(r + 8) * Nd + col) = o;
            }
        }
    }
}

// ---------------------------------------------------------------------------
// att = softmax(h2 @ W3 + b3), accumulates att_sum into g_S0
// ---------------------------------------------------------------------------
__global__ void __launch_bounds__(256)
attn_softmax_kernel(const float* __restrict__ W3, const float* __restrict__ b3)
{
    __shared__ float sW[H2DIM * KCOMP];
    __shared__ float sh[8][H2DIM];
    __shared__ float ssum[KCOMP];

    const int tid  = threadIdx.x;
    const int wid  = tid >> 5;
    const int lane = tid & 31;

    for (int i = tid; i < H2DIM * KCOMP; i += 256) sW[i] = W3[i];
    if (tid < KCOMP) ssum[tid] = 0.f;
    float bk = b3[lane];
    __syncthreads();

    for (int row = blockIdx.x * 8 + wid; row < NROWS; row += gridDim.x * 8) {
#pragma unroll
        for (int q = 0; q < 8; q++)
            sh[wid][lane + q * 32] = g_h2[(size_t)row * H2DIM + lane + q * 32];
        __syncwarp();

        float acc = bk;
#pragma unroll 8
        for (int j = 0; j < H2DIM; j++)
            acc = fmaf(sh[wid][j], sW[j * KCOMP + lane], acc);

        float m = acc;
#pragma unroll
        for (int o = 16; o > 0; o >>= 1) m = fmaxf(m, __shfl_xor_sync(0xffffffffu, m, o));
        float e = expf(acc - m);
        float s = e;
#pragma unroll
        for (int o = 16; o > 0; o >>= 1) s += __shfl_xor_sync(0xffffffffu, s, o);
        float p = e / s;

        g_att[(size_t)row * KCOMP + lane] = p;
        atomicAdd(&ssum[lane], p);
        __syncwarp();
    }

    __syncthreads();
    if (tid < KCOMP) atomicAdd(&g_S0[tid], ssum[tid]);
}

// ---------------------------------------------------------------------------
// Weighted stats
// ---------------------------------------------------------------------------
#define STAT_ROWS 2048
__global__ void __launch_bounds__(128)
stats_kernel(const float* __restrict__ x)
{
    __shared__ float sa[32][32];

    const int tid = threadIdx.x;
    const int dl  = tid & 63;
    const int kh  = tid >> 6;
    const int d   = blockIdx.y * 64 + dl;
    const int n0  = blockIdx.x * STAT_ROWS;

    float s1[16], s2[16];
#pragma unroll
    for (int i = 0; i < 16; i++) { s1[i] = 0.f; s2[i] = 0.f; }

    for (int rb = 0; rb < STAT_ROWS; rb += 32) {
#pragma unroll
        for (int q = 0; q < 8; q++) {
            int idx = tid + q * 128;
            int r = n0 + rb + (idx >> 5);
            sa[idx >> 5][idx & 31] = (r < NROWS) ? g_att[(size_t)r * KCOMP + (idx & 31)] : 0.f;
        }
        __syncthreads();

#pragma unroll 4
        for (int rr = 0; rr < 32; rr++) {
            int row = n0 + rb + rr;
            float xv = (row < NROWS) ? x[(size_t)row * DDIM + d] : 0.f;
            float x2 = xv * xv;
            const float* ap = &sa[rr][kh * 16];
#pragma unroll
            for (int i = 0; i < 16; i++) {
                float a = ap[i];
                s1[i] = fmaf(a, xv, s1[i]);
                s2[i] = fmaf(a, x2, s2[i]);
            }
        }
        __syncthreads();
    }

#pragma unroll
    for (int i = 0; i < 16; i++) {
        int k = kh * 16 + i;
        atomicAdd(&g_S1[k * DDIM + d], s1[i]);
        atomicAdd(&g_S2[k * DDIM + d], s2[i]);
    }
}

// ---------------------------------------------------------------------------
// Finalize per-component params; write vars
// ---------------------------------------------------------------------------
__global__ void __launch_bounds__(256)
finalize_kernel(float* __restrict__ out_vars)
{
    const int k = blockIdx.x;
    const int t = threadIdx.x;
    const float inv_s0 = 1.0f / g_S0[k];

    float csum = 0.f;
    for (int d = t; d < DDIM; d += 256) {
        float mean = g_S1[k * DDIM + d] * inv_s0;
        float ex2  = g_S2[k * DDIM + d] * inv_s0;
        float var  = ex2 - mean * mean;
        float iv   = 1.0f / var;
        float miv  = mean * iv;
        out_vars[k * DDIM + d] = var;
        g_pivmiv[d * KCOMP + k] = make_float2(iv, miv);
        csum += mean * miv + logf(var);
    }

    __shared__ float red[256];
    red[t] = csum;
    __syncthreads();
    if (t < 128) red[t] += red[t + 128];
    __syncthreads();
    if (t < 64) red[t] += red[t + 64];
    __syncthreads();
    if (t < 32) {
        float v = red[t] + red[t + 32];
#pragma unroll
        for (int o = 16; o > 0; o >>= 1) v += __shfl_xor_sync(0xffffffffu, v, o);
        if (t == 0)
            g_Ck[k] = -0.5f * v - (float)DDIM * 0.9189385332046727f;
    }
}

// ---------------------------------------------------------------------------
// Final GMM log-likelihood
// ---------------------------------------------------------------------------
template <bool GUARD>
__device__ __forceinline__ void gmm_out_body(const float* __restrict__ x,
                                             float* __restrict__ out,
                                             int base, int lane, float ck)
{
    float acc[16];
#pragma unroll
    for (int r = 0; r < 16; r++) acc[r] = 0.f;

    for (int c = 0; c < 16; c++) {
        float2 pm[32];
#pragma unroll
        for (int j = 0; j < 32; j++)
            pm[j] = g_pivmiv[(c * 32 + j) * KCOMP + lane];

#pragma unroll
        for (int r = 0; r < 16; r++) {
            if (GUARD && (base + r >= NROWS)) continue;
            const float4* xp = (const float4*)(x + (size_t)(base + r) * DDIM + c * 32);
#pragma unroll
            for (int q = 0; q < 8; q++) {
                float4 xq = xp[q];
                {
                    float xv = xq.x, xh = -0.5f * xv;
                    float tt = fmaf(xh, pm[q * 4 + 0].x, pm[q * 4 + 0].y);
                    acc[r] = fmaf(xv, tt, acc[r]);
                }
                {
                    float xv = xq.y, xh = -0.5f * xv;
                    float tt = fmaf(xh, pm[q * 4 + 1].x, pm[q * 4 + 1].y);
                    acc[r] = fmaf(xv, tt, acc[r]);
                }
                {
                    float xv = xq.z, xh = -0.5f * xv;
                    float tt = fmaf(xh, pm[q * 4 + 2].x, pm[q * 4 + 2].y);
                    acc[r] = fmaf(xv, tt, acc[r]);
                }
                {
                    float xv = xq.w, xh = -0.5f * xv;
                    float tt = fmaf(xh, pm[q * 4 + 3].x, pm[q * 4 + 3].y);
                    acc[r] = fmaf(xv, tt, acc[r]);
                }
            }
        }
    }

#pragma unroll
    for (int r = 0; r < 16; r++) {
        int row = base + r;
        if (!GUARD || row < NROWS)
            out[(size_t)row * KCOMP + lane] = acc[r] + ck;
    }
}

__global__ void __launch_bounds__(128)
gmm_out_kernel(const float* __restrict__ x, float* __restrict__ out)
{
    const int lane = threadIdx.x & 31;
    const int w = blockIdx.x * 4 + (threadIdx.x >> 5);
    const int base = w * 16;
    if (base >= NROWS) return;
    const float ck = g_Ck[lane];

    if (base + 16 <= NROWS)
        gmm_out_body<false>(x, out, base, lane, ck);
    else
        gmm_out_body<true>(x, out, base, lane, ck);
}

// ---------------------------------------------------------------------------
// Launch
// ---------------------------------------------------------------------------
extern "C" void kernel_launch(void* const* d_in, const int* in_sizes, int n_in,
                              void* d_out, int out_size)
{
    const float* x  = (const float*)d_in[0];
    const float* W1 = (const float*)d_in[1];
    const float* b1 = (const float*)d_in[2];
    const float* W2 = (const float*)d_in[3];
    const float* b2 = (const float*)d_in[4];
    const float* W3 = (const float*)d_in[5];
    const float* b3 = (const float*)d_in[6];
    float* out = (float*)d_out;

    float *h1p = nullptr, *h2p = nullptr, *w1tp = nullptr, *w2tp = nullptr;
    cudaGetSymbolAddress((void**)&h1p, g_h1);
    cudaGetSymbolAddress((void**)&h2p, g_h2);
    cudaGetSymbolAddress((void**)&w1tp, g_W1t);
    cudaGetSymbolAddress((void**)&w2tp, g_W2t);

    cudaFuncSetAttribute(gemm_mma, cudaFuncAttributeMaxDynamicSharedMemorySize, GEMM_SMEM);

    // 0) zero accumulators + transpose weights (tf32 RN)
    zero_kernel<<<64, 256>>>();
    transpose_tf32<<<dim3(512 / 32, 512 / 32), dim3(32, 8)>>>(W1, w1tp, DDIM, H1DIM);
    transpose_tf32<<<dim3(256 / 32, 512 / 32), dim3(32, 8)>>>(W2, w2tp, H1DIM, H2DIM);

    const int mtiles = (NROWS + BM - 1) / BM;  // 782

    // 1) h1 = softplus(x @ W1 + b1)   [tf32 mma.sync]
    gemm_mma<<<dim3(mtiles, H1DIM / BN), 256, GEMM_SMEM>>>(x, w1tp, b1, h1p, NROWS, H1DIM);

    // 2) h2 = softplus(h1 @ W2 + b2)  [tf32 mma.sync]
    gemm_mma<<<dim3(mtiles, H2DIM / BN), 256, GEMM_SMEM>>>(h1p, w2tp, b2, h2p, NROWS, H2DIM);

    // 3) att = softmax(h2 @ W3 + b3)
    attn_softmax_kernel<<<1250, 256>>>(W3, b3);

    // 4) weighted stats
    {
        dim3 grid((NROWS + STAT_ROWS - 1) / STAT_ROWS, DDIM / 64);
        stats_kernel<<<grid, 128>>>(x);
    }

    // 5) finalize params + vars output
    finalize_kernel<<<KCOMP, 256>>>(out + (size_t)NROWS * KCOMP);

    // 6) GMM log-likelihood output
    {
        int nblocks = (NROWS + 63) / 64;
        gmm_out_kernel<<<nblocks, 128>>>(x, out);
    }
}

// round 4
// speedup vs baseline: 2.6727x; 1.3795x over previous
#include <cuda_runtime.h>
#include <cuda_fp16.h>
#include <math.h>
#include <stdint.h>

#define NROWS 100000
#define DDIM  512
#define KCOMP 32
#define H1DIM 512
#define H2DIM 256

// ---------------------------------------------------------------------------
// Device scratch
// ---------------------------------------------------------------------------
__device__ __half g_h1h[(size_t)NROWS * H1DIM];   // 102.4 MB
__device__ __half g_h2h[(size_t)NROWS * H2DIM];   // 51.2 MB
__device__ float  g_att[(size_t)NROWS * KCOMP];   // 12.8 MB
__device__ float  g_S0[KCOMP];
__device__ float  g_S1[KCOMP * DDIM];
__device__ float  g_S2[KCOMP * DDIM];
__device__ float  g_Ck[KCOMP];
__device__ __half g_W1th[(size_t)H1DIM * DDIM];   // W1^T [n][k] fp16
__device__ __half g_W2th[(size_t)H2DIM * H1DIM];  // W2^T [n][k] fp16
__device__ __half g_Bm[KCOMP * DDIM];             // miv       [k][d] fp16
__device__ __half g_Bv[KCOMP * DDIM];             // -0.5*iv   [k][d] fp16

__device__ __forceinline__ float softplusf(float v) {
    return fmaxf(v, 0.f) + log1pf(expf(-fabsf(v)));
}
__device__ __forceinline__ uint32_t smem_u32(const void* p) {
    uint32_t a;
    asm("{ .reg .u64 t; cvta.to.shared.u64 t, %1; cvt.u32.u64 %0, t; }"
        : "=r"(a) : "l"(p));
    return a;
}
__device__ __forceinline__ void ldmx4(uint32_t* r, uint32_t addr) {
    asm volatile("ldmatrix.sync.aligned.m8n8.x4.shared.b16 {%0,%1,%2,%3}, [%4];"
        : "=r"(r[0]), "=r"(r[1]), "=r"(r[2]), "=r"(r[3]) : "r"(addr));
}
__device__ __forceinline__ void mma_f16(float* c, const uint32_t* a, const uint32_t* b) {
    asm volatile("mma.sync.aligned.m16n8k16.row.col.f32.f16.f16.f32 "
        "{%0,%1,%2,%3}, {%4,%5,%6,%7}, {%8,%9}, {%0,%1,%2,%3};"
        : "+f"(c[0]), "+f"(c[1]), "+f"(c[2]), "+f"(c[3])
        : "r"(a[0]), "r"(a[1]), "r"(a[2]), "r"(a[3]), "r"(b[0]), "r"(b[1]));
}

// ---------------------------------------------------------------------------
__global__ void zero_kernel() {
    int i = blockIdx.x * blockDim.x + threadIdx.x;
    if (i < KCOMP) g_S0[i] = 0.f;
    if (i < KCOMP * DDIM) { g_S1[i] = 0.f; g_S2[i] = 0.f; }
}

// Transpose W [K][Nd] -> Wt [Nd][K] fp16
__global__ void transpose_h(const float* __restrict__ W, __half* __restrict__ Wt,
                            int K, int Nd)
{
    __shared__ float t[32][33];
    int n0 = blockIdx.x * 32, k0 = blockIdx.y * 32;
    int x = threadIdx.x, y = threadIdx.y;
    for (int i = y; i < 32; i += 8) {
        int k = k0 + i, n = n0 + x;
        t[i][x] = (k < K && n < Nd) ? W[(size_t)k * Nd + n] : 0.f;
    }
    __syncthreads();
    for (int i = y; i < 32; i += 8) {
        int n = n0 + i, k = k0 + x;
        if (n < Nd && k < K)
            Wt[(size_t)n * K + k] = __float2half_rn(t[x][i]);
    }
}

// ---------------------------------------------------------------------------
// fp16 GEMM + bias + softplus, fp16 output
//   C[M,Nd] = softplus(A[M,512] @ Bt[Nd,512]^T + bias)
// BM=128, BN=128, BK=32 halves, 256 thr, 8 warps (4m x 2n), ldmatrix+mma k16.
// ---------------------------------------------------------------------------
#define AST  40                       // halves stride (80B: conflict-free ldmatrix)
#define ASTB 80
#define STGH (128 * AST)              // halves per stage
#define STGB (STGH * 2)               // bytes per stage (10240)
#define GEMM_SMEM (4 * STGB)          // 2 stages x (A+B) = 40960 B

template<bool AFP32>
__global__ void __launch_bounds__(256)
gemm_h(const void* __restrict__ Ain, const __half* __restrict__ Bt,
       const float* __restrict__ bias, __half* __restrict__ C,
       int M, int Nd)
{
    extern __shared__ char smraw[];
    __half* Asm = (__half*)smraw;                    // [2][128][AST]
    __half* Bsm = (__half*)(smraw + 2 * STGB);
    const uint32_t sb = smem_u32(smraw);

    const int tid = threadIdx.x, lane = tid & 31, warp = tid >> 5;
    const int wm = warp >> 1, wn = warp & 1;
    const int m0 = blockIdx.y * 128, n0 = blockIdx.x * 128;

    const float*  A32 = (const float*)Ain;
    const __half* A16 = (const __half*)Ain;

    float acc[2][8][4];
#pragma unroll
    for (int i = 0; i < 2; i++)
#pragma unroll
        for (int j = 0; j < 8; j++)
#pragma unroll
            for (int q = 0; q < 4; q++) acc[i][j][q] = 0.f;

    int ra[4];
#pragma unroll
    for (int q = 0; q < 4; q++) ra[q] = (tid + 256 * q) >> 3;
    const int c4 = (tid & 7) * 4;
    const int rh[2] = { tid >> 2, (tid + 256) >> 2 };
    const int c8 = (tid & 3) * 8;

    // ---- prologue: chunk 0 -> stage 0 ----
    if (AFP32) {
#pragma unroll
        for (int q = 0; q < 4; q++) {
            int r = ra[q];
            float4 v = (m0 + r < M) ? *(const float4*)(A32 + (size_t)(m0 + r) * 512 + c4)
                                    : make_float4(0.f, 0.f, 0.f, 0.f);
            __half2* d = (__half2*)(Asm + r * AST + c4);
            d[0] = __floats2half2_rn(v.x, v.y);
            d[1] = __floats2half2_rn(v.z, v.w);
        }
    } else {
#pragma unroll
        for (int q = 0; q < 2; q++) {
            int r = rh[q];
            uint4 v = (m0 + r < M) ? *(const uint4*)(A16 + (size_t)(m0 + r) * 512 + c8)
                                   : make_uint4(0, 0, 0, 0);
            *(uint4*)(Asm + r * AST + c8) = v;
        }
    }
#pragma unroll
    for (int q = 0; q < 2; q++) {
        int r = rh[q];
        *(uint4*)(Bsm + r * AST + c8) = *(const uint4*)(Bt + (size_t)(n0 + r) * 512 + c8);
    }
    __syncthreads();

    const uint32_t aoff = sb + (wm * 32 + (lane & 15)) * ASTB + (lane >> 4) * 16;
    const uint32_t boff = sb + 2 * STGB
                        + (wn * 64 + (lane & 7) + ((lane >> 4) << 3)) * ASTB
                        + ((lane >> 3) & 1) * 16;

    for (int c = 0; c < 16; c++) {
        const int s = c & 1;
        float4 pa32[4]; uint4 pa16[2]; uint4 pb[2];
        if (c < 15) {
            int k0 = (c + 1) * 32;
            if (AFP32) {
#pragma unroll
                for (int q = 0; q < 4; q++) {
                    int r = ra[q];
                    pa32[q] = (m0 + r < M) ? *(const float4*)(A32 + (size_t)(m0 + r) * 512 + k0 + c4)
                                           : make_float4(0.f, 0.f, 0.f, 0.f);
                }
            } else {
#pragma unroll
                for (int q = 0; q < 2; q++) {
                    int r = rh[q];
                    pa16[q] = (m0 + r < M) ? *(const uint4*)(A16 + (size_t)(m0 + r) * 512 + k0 + c8)
                                           : make_uint4(0, 0, 0, 0);
                }
            }
#pragma unroll
            for (int q = 0; q < 2; q++) {
                int r = rh[q];
                pb[q] = *(const uint4*)(Bt + (size_t)(n0 + r) * 512 + k0 + c8);
            }
        }

        const uint32_t ab = aoff + s * STGB;
        const uint32_t bb = boff + s * STGB;
#pragma unroll
        for (int ks = 0; ks < 2; ks++) {
            uint32_t a0[4], a1[4];
            ldmx4(a0, ab + ks * 32);
            ldmx4(a1, ab + ks * 32 + 16 * ASTB);
#pragma unroll
            for (int p = 0; p < 4; p++) {
                uint32_t br[4];
                ldmx4(br, bb + ks * 32 + p * 16 * ASTB);
                mma_f16(acc[0][2 * p],     a0, br);
                mma_f16(acc[0][2 * p + 1], a0, br + 2);
                mma_f16(acc[1][2 * p],     a1, br);
                mma_f16(acc[1][2 * p + 1], a1, br + 2);
            }
        }

        if (c < 15) {
            __half* Ad = Asm + (s ^ 1) * STGH;
            __half* Bd = Bsm + (s ^ 1) * STGH;
            if (AFP32) {
#pragma unroll
                for (int q = 0; q < 4; q++) {
                    __half2* d = (__half2*)(Ad + ra[q] * AST + c4);
                    d[0] = __floats2half2_rn(pa32[q].x, pa32[q].y);
                    d[1] = __floats2half2_rn(pa32[q].z, pa32[q].w);
                }
            } else {
#pragma unroll
                for (int q = 0; q < 2; q++)
                    *(uint4*)(Ad + rh[q] * AST + c8) = pa16[q];
            }
#pragma unroll
            for (int q = 0; q < 2; q++)
                *(uint4*)(Bd + rh[q] * AST + c8) = pb[q];
            __syncthreads();
        }
    }

    // ---- epilogue ----
    const int gid = lane >> 2, tig = lane & 3;
#pragma unroll
    for (int i = 0; i < 2; i++) {
        int r = m0 + wm * 32 + i * 16 + gid;
#pragma unroll
        for (int j = 0; j < 8; j++) {
            int col = n0 + wn * 64 + j * 8 + 2 * tig;
            float b0 = __ldg(bias + col), b1 = __ldg(bias + col + 1);
            if (r < M)
                *(__half2*)(C + (size_t)r * Nd + col) =
                    __floats2half2_rn(softplusf(acc[i][j][0] + b0),
                                      softplusf(acc[i][j][1] + b1));
            if (r + 8 < M)
                *(__half2*)(C + (size_t)(r + 8) * Nd + col) =
                    __floats2half2_rn(softplusf(acc[i][j][2] + b0),
                                      softplusf(acc[i][j][3] + b1));
        }
    }
}

// ---------------------------------------------------------------------------
// att = softmax(h2 @ W3 + b3); h2 in fp16
// ---------------------------------------------------------------------------
__global__ void __launch_bounds__(256)
attn_softmax_kernel(const float* __restrict__ W3, const float* __restrict__ b3)
{
    __shared__ float sW[H2DIM * KCOMP];
    __shared__ float sh[8][H2DIM];
    __shared__ float ssum[KCOMP];

    const int tid = threadIdx.x, wid = tid >> 5, lane = tid & 31;

    for (int i = tid; i < H2DIM * KCOMP; i += 256) sW[i] = W3[i];
    if (tid < KCOMP) ssum[tid] = 0.f;
    float bk = b3[lane];
    __syncthreads();

    for (int row = blockIdx.x * 8 + wid; row < NROWS; row += gridDim.x * 8) {
        const __half2* hp = (const __half2*)g_h2h + (size_t)row * (H2DIM / 2);
#pragma unroll
        for (int q = 0; q < 4; q++) {
            float2 f = __half22float2(hp[lane + q * 32]);
            sh[wid][(lane + q * 32) * 2]     = f.x;
            sh[wid][(lane + q * 32) * 2 + 1] = f.y;
        }
        __syncwarp();

        float acc = bk;
#pragma unroll 8
        for (int j = 0; j < H2DIM; j++)
            acc = fmaf(sh[wid][j], sW[j * KCOMP + lane], acc);

        float m = acc;
#pragma unroll
        for (int o = 16; o > 0; o >>= 1) m = fmaxf(m, __shfl_xor_sync(0xffffffffu, m, o));
        float e = expf(acc - m);
        float s = e;
#pragma unroll
        for (int o = 16; o > 0; o >>= 1) s += __shfl_xor_sync(0xffffffffu, s, o);
        float p = e / s;

        g_att[(size_t)row * KCOMP + lane] = p;
        atomicAdd(&ssum[lane], p);
        __syncwarp();
    }

    __syncthreads();
    if (tid < KCOMP) atomicAdd(&g_S0[tid], ssum[tid]);
}

// ---------------------------------------------------------------------------
// Weighted stats (unchanged; fp32 exact inputs)
// ---------------------------------------------------------------------------
#define STAT_ROWS 2048
__global__ void __launch_bounds__(128)
stats_kernel(const float* __restrict__ x)
{
    __shared__ float sa[32][32];

    const int tid = threadIdx.x;
    const int dl = tid & 63, kh = tid >> 6;
    const int d = blockIdx.y * 64 + dl;
    const int n0 = blockIdx.x * STAT_ROWS;

    float s1[16], s2[16];
#pragma unroll
    for (int i = 0; i < 16; i++) { s1[i] = 0.f; s2[i] = 0.f; }

    for (int rb = 0; rb < STAT_ROWS; rb += 32) {
#pragma unroll
        for (int q = 0; q < 8; q++) {
            int idx = tid + q * 128;
            int r = n0 + rb + (idx >> 5);
            sa[idx >> 5][idx & 31] = (r < NROWS) ? g_att[(size_t)r * KCOMP + (idx & 31)] : 0.f;
        }
        __syncthreads();

#pragma unroll 4
        for (int rr = 0; rr < 32; rr++) {
            int row = n0 + rb + rr;
            float xv = (row < NROWS) ? x[(size_t)row * DDIM + d] : 0.f;
            float x2 = xv * xv;
            const float* ap = &sa[rr][kh * 16];
#pragma unroll
            for (int i = 0; i < 16; i++) {
                float a = ap[i];
                s1[i] = fmaf(a, xv, s1[i]);
                s2[i] = fmaf(a, x2, s2[i]);
            }
        }
        __syncthreads();
    }

#pragma unroll
    for (int i = 0; i < 16; i++) {
        int k = kh * 16 + i;
        atomicAdd(&g_S1[k * DDIM + d], s1[i]);
        atomicAdd(&g_S2[k * DDIM + d], s2[i]);
    }
}

// ---------------------------------------------------------------------------
// Finalize params; writes vars output + fp16 B matrices for the maha GEMM
// ---------------------------------------------------------------------------
__global__ void __launch_bounds__(256)
finalize_kernel(float* __restrict__ out_vars)
{
    const int k = blockIdx.x;
    const int t = threadIdx.x;
    const float inv_s0 = 1.0f / g_S0[k];

    float csum = 0.f;
    for (int d = t; d < DDIM; d += 256) {
        float mean = g_S1[k * DDIM + d] * inv_s0;
        float ex2  = g_S2[k * DDIM + d] * inv_s0;
        float var  = ex2 - mean * mean;
        float iv   = 1.0f / var;
        float miv  = mean * iv;
        out_vars[k * DDIM + d] = var;
        g_Bm[k * DDIM + d] = __float2half_rn(miv);
        g_Bv[k * DDIM + d] = __float2half_rn(-0.5f * iv);
        csum += mean * miv + logf(var);
    }

    __shared__ float red[256];
    red[t] = csum;
    __syncthreads();
    if (t < 128) red[t] += red[t + 128];
    __syncthreads();
    if (t < 64) red[t] += red[t + 64];
    __syncthreads();
    if (t < 32) {
        float v = red[t] + red[t + 32];
#pragma unroll
        for (int o = 16; o > 0; o >>= 1) v += __shfl_xor_sync(0xffffffffu, v, o);
        if (t == 0)
            g_Ck[k] = -0.5f * v - (float)DDIM * 0.9189385332046727f;
    }
}

// ---------------------------------------------------------------------------
// Tensorized GMM output: out[n,k] = x@Bm^T + x^2@Bv^T + Ck
// BM=128 rows/block, 8 warps each m16, full K=32 cols per warp.
// ---------------------------------------------------------------------------
#define GASTG (128 * AST)          // A stage halves
#define GBSTG (32 * AST)           // B stage halves
#define GAXB  0
#define GAX2B (2 * GASTG * 2)      // 20480
#define GBMB  (GAX2B + 2 * GASTG * 2)  // 40960
#define GBVB  (GBMB + 2 * GBSTG * 2)   // 46080
#define GMM_SMEM (GBVB + 2 * GBSTG * 2)  // 51200

__global__ void __launch_bounds__(256)
gmm_mma(const float* __restrict__ x, float* __restrict__ out)
{
    extern __shared__ char smraw[];
    __half* Ax  = (__half*)(smraw + GAXB);
    __half* Ax2 = (__half*)(smraw + GAX2B);
    __half* Bms = (__half*)(smraw + GBMB);
    __half* Bvs = (__half*)(smraw + GBVB);
    __shared__ float sck[KCOMP];
    const uint32_t sb = smem_u32(smraw);

    const int tid = threadIdx.x, lane = tid & 31, w = tid >> 5;
    const int m0 = blockIdx.x * 128;

    if (tid < KCOMP) sck[tid] = g_Ck[tid];

    float acc[4][4];
#pragma unroll
    for (int j = 0; j < 4; j++)
#pragma unroll
        for (int q = 0; q < 4; q++) acc[j][q] = 0.f;

    int ra[4];
#pragma unroll
    for (int q = 0; q < 4; q++) ra[q] = (tid + 256 * q) >> 3;
    const int c4 = (tid & 7) * 4;

    const int tl = tid & 127;
    const int rb = tl >> 2;
    const int cb = (tl & 3) * 8;
    const bool isv = tid >= 128;
    const __half* Bg = isv ? g_Bv : g_Bm;
    __half* Bs = isv ? Bvs : Bms;

    // prologue
#pragma unroll
    for (int q = 0; q < 4; q++) {
        int r = ra[q];
        float4 v = (m0 + r < NROWS) ? *(const float4*)(x + (size_t)(m0 + r) * 512 + c4)
                                    : make_float4(0.f, 0.f, 0.f, 0.f);
        __half2* d = (__half2*)(Ax + r * AST + c4);
        d[0] = __floats2half2_rn(v.x, v.y);
        d[1] = __floats2half2_rn(v.z, v.w);
        __half2* d2 = (__half2*)(Ax2 + r * AST + c4);
        d2[0] = __floats2half2_rn(v.x * v.x, v.y * v.y);
        d2[1] = __floats2half2_rn(v.z * v.z, v.w * v.w);
    }
    *(uint4*)(Bs + rb * AST + cb) = *(const uint4*)(Bg + rb * 512 + cb);
    __syncthreads();

    const uint32_t aoffx  = sb + GAXB  + (w * 16 + (lane & 15)) * ASTB + (lane >> 4) * 16;
    const uint32_t aoffx2 = sb + GAX2B + (w * 16 + (lane & 15)) * ASTB + (lane >> 4) * 16;
    const uint32_t boffm  = sb + GBMB + ((lane & 7) + ((lane >> 4) << 3)) * ASTB + ((lane >> 3) & 1) * 16;
    const uint32_t boffv  = sb + GBVB + ((lane & 7) + ((lane >> 4) << 3)) * ASTB + ((lane >> 3) & 1) * 16;

    for (int c = 0; c < 16; c++) {
        const int s = c & 1;
        float4 pa[4]; uint4 pbb;
        if (c < 15) {
            int k0 = (c + 1) * 32;
#pragma unroll
            for (int q = 0; q < 4; q++) {
                int r = ra[q];
                pa[q] = (m0 + r < NROWS) ? *(const float4*)(x + (size_t)(m0 + r) * 512 + k0 + c4)
                                         : make_float4(0.f, 0.f, 0.f, 0.f);
            }
            pbb = *(const uint4*)(Bg + rb * 512 + k0 + cb);
        }

        const uint32_t axb  = aoffx  + s * (GASTG * 2);
        const uint32_t ax2b = aoffx2 + s * (GASTG * 2);
        const uint32_t bmb  = boffm  + s * (GBSTG * 2);
        const uint32_t bvb  = boffv  + s * (GBSTG * 2);
#pragma unroll
        for (int ks = 0; ks < 2; ks++) {
            uint32_t ax[4], ax2[4];
            ldmx4(ax,  axb  + ks * 32);
            ldmx4(ax2, ax2b + ks * 32);
#pragma unroll
            for (int p = 0; p < 2; p++) {
                uint32_t bm[4], bv[4];
                ldmx4(bm, bmb + ks * 32 + p * 16 * ASTB);
                mma_f16(acc[2 * p],     ax, bm);
                mma_f16(acc[2 * p + 1], ax, bm + 2);
                ldmx4(bv, bvb + ks * 32 + p * 16 * ASTB);
                mma_f16(acc[2 * p],     ax2, bv);
                mma_f16(acc[2 * p + 1], ax2, bv + 2);
            }
        }

        if (c < 15) {
            __half* Axd  = Ax  + (s ^ 1) * GASTG;
            __half* Ax2d = Ax2 + (s ^ 1) * GASTG;
#pragma unroll
            for (int q = 0; q < 4; q++) {
                __half2* d = (__half2*)(Axd + ra[q] * AST + c4);
                d[0] = __floats2half2_rn(pa[q].x, pa[q].y);
                d[1] = __floats2half2_rn(pa[q].z, pa[q].w);
                __half2* d2 = (__half2*)(Ax2d + ra[q] * AST + c4);
                d2[0] = __floats2half2_rn(pa[q].x * pa[q].x, pa[q].y * pa[q].y);
                d2[1] = __floats2half2_rn(pa[q].z * pa[q].z, pa[q].w * pa[q].w);
            }
            *(uint4*)(Bs + (s ^ 1) * GBSTG + rb * AST + cb) = pbb;
            __syncthreads();
        }
    }

    // epilogue
    const int gid = lane >> 2, tig = lane & 3;
    const int r0 = m0 + w * 16 + gid;
#pragma unroll
    for (int j = 0; j < 4; j++) {
        int col = j * 8 + 2 * tig;
        float ck0 = sck[col], ck1 = sck[col + 1];
        if (r0 < NROWS) {
            float2 o = { acc[j][0] + ck0, acc[j][1] + ck1 };
            *(float2*)(out + (size_t)r0 * KCOMP + col) = o;
        }
        if (r0 + 8 < NROWS) {
            float2 o = { acc[j][2] + ck0, acc[j][3] + ck1 };
            *(float2*)(out + (size_t)(r0 + 8) * KCOMP + col) = o;
        }
    }
}

// ---------------------------------------------------------------------------
// Launch
// ---------------------------------------------------------------------------
extern "C" void kernel_launch(void* const* d_in, const int* in_sizes, int n_in,
                              void* d_out, int out_size)
{
    const float* x  = (const float*)d_in[0];
    const float* W1 = (const float*)d_in[1];
    const float* b1 = (const float*)d_in[2];
    const float* W2 = (const float*)d_in[3];
    const float* b2 = (const float*)d_in[4];
    const float* W3 = (const float*)d_in[5];
    const float* b3 = (const float*)d_in[6];
    float* out = (float*)d_out;

    __half *h1p = nullptr, *h2p = nullptr, *w1tp = nullptr, *w2tp = nullptr;
    cudaGetSymbolAddress((void**)&h1p, g_h1h);
    cudaGetSymbolAddress((void**)&h2p, g_h2h);
    cudaGetSymbolAddress((void**)&w1tp, g_W1th);
    cudaGetSymbolAddress((void**)&w2tp, g_W2th);

    cudaFuncSetAttribute(gemm_h<true>,  cudaFuncAttributeMaxDynamicSharedMemorySize, GEMM_SMEM);
    cudaFuncSetAttribute(gemm_h<false>, cudaFuncAttributeMaxDynamicSharedMemorySize, GEMM_SMEM);
    cudaFuncSetAttribute(gmm_mma, cudaFuncAttributeMaxDynamicSharedMemorySize, GMM_SMEM);

    zero_kernel<<<64, 256>>>();
    transpose_h<<<dim3(H1DIM / 32, DDIM / 32), dim3(32, 8)>>>(W1, w1tp, DDIM, H1DIM);
    transpose_h<<<dim3(H2DIM / 32, H1DIM / 32), dim3(32, 8)>>>(W2, w2tp, H1DIM, H2DIM);

    const int mtiles = (NROWS + 127) / 128;  // 782

    // 1) h1 = softplus(x @ W1 + b1)   [fp16 mma, grid.x = n-tiles for L2 reuse]
    gemm_h<true><<<dim3(H1DIM / 128, mtiles), 256, GEMM_SMEM>>>(x, w1tp, b1, h1p, NROWS, H1DIM);

    // 2) h2 = softplus(h1 @ W2 + b2)
    gemm_h<false><<<dim3(H2DIM / 128, mtiles), 256, GEMM_SMEM>>>(h1p, w2tp, b2, h2p, NROWS, H2DIM);

    // 3) att = softmax(h2 @ W3 + b3)
    attn_softmax_kernel<<<1250, 256>>>(W3, b3);

    // 4) weighted stats
    {
        dim3 grid((NROWS + STAT_ROWS - 1) / STAT_ROWS, DDIM / 64);
        stats_kernel<<<grid, 128>>>(x);
    }

    // 5) finalize: vars output + Bm/Bv/Ck
    finalize_kernel<<<KCOMP, 256>>>(out + (size_t)NROWS * KCOMP);

    // 6) maha GEMM output
    gmm_mma<<<mtiles, 256, GMM_SMEM>>>(x, out);
}

// round 5
// speedup vs baseline: 5.6942x; 2.1305x over previous
#include <cuda_runtime.h>
#include <cuda_fp16.h>
#include <math.h>
#include <stdint.h>

#define NROWS 100000
#define DDIM  512
#define KCOMP 32
#define H1DIM 512
#define H2DIM 256

// ---------------------------------------------------------------------------
// Device scratch
// ---------------------------------------------------------------------------
__device__ __half g_xh [(size_t)NROWS * DDIM];    // x fp16, 102.4 MB
__device__ __half g_h1h[(size_t)NROWS * H1DIM];   // 102.4 MB
__device__ __half g_h2h[(size_t)NROWS * H2DIM];   // 51.2 MB
__device__ __half g_atth[(size_t)NROWS * KCOMP];  // 6.4 MB
__device__ float  g_S0[KCOMP];
__device__ float  g_S1[KCOMP * DDIM];
__device__ float  g_S2[KCOMP * DDIM];
__device__ float  g_Ck[KCOMP];
__device__ __half g_W1th[(size_t)H1DIM * DDIM];
__device__ __half g_W2th[(size_t)H2DIM * H1DIM];
__device__ __half g_W3th[(size_t)KCOMP * H2DIM];
__device__ __half g_Bm[KCOMP * DDIM];             // miv
__device__ __half g_Bv[KCOMP * DDIM];             // -0.5*iv

__device__ __forceinline__ float softplusf(float v) {
    return fmaxf(v, 0.f) + log1pf(expf(-fabsf(v)));
}
__device__ __forceinline__ uint32_t smem_u32(const void* p) {
    uint32_t a;
    asm("{ .reg .u64 t; cvta.to.shared.u64 t, %1; cvt.u32.u64 %0, t; }"
        : "=r"(a) : "l"(p));
    return a;
}
__device__ __forceinline__ void ldmx4(uint32_t* r, uint32_t addr) {
    asm volatile("ldmatrix.sync.aligned.m8n8.x4.shared.b16 {%0,%1,%2,%3}, [%4];"
        : "=r"(r[0]), "=r"(r[1]), "=r"(r[2]), "=r"(r[3]) : "r"(addr));
}
__device__ __forceinline__ void ldmx4t(uint32_t* r, uint32_t addr) {
    asm volatile("ldmatrix.sync.aligned.m8n8.x4.trans.shared.b16 {%0,%1,%2,%3}, [%4];"
        : "=r"(r[0]), "=r"(r[1]), "=r"(r[2]), "=r"(r[3]) : "r"(addr));
}
__device__ __forceinline__ void mma_f16(float* c, const uint32_t* a, const uint32_t* b) {
    asm volatile("mma.sync.aligned.m16n8k16.row.col.f32.f16.f16.f32 "
        "{%0,%1,%2,%3}, {%4,%5,%6,%7}, {%8,%9}, {%0,%1,%2,%3};"
        : "+f"(c[0]), "+f"(c[1]), "+f"(c[2]), "+f"(c[3])
        : "r"(a[0]), "r"(a[1]), "r"(a[2]), "r"(a[3]), "r"(b[0]), "r"(b[1]));
}
__device__ __forceinline__ uint32_t sqh2(uint32_t v) {
    __half2 h = *(__half2*)&v;
    __half2 o = __hmul2(h, h);
    return *(uint32_t*)&o;
}

// ---------------------------------------------------------------------------
__global__ void zero_kernel() {
    int i = blockIdx.x * blockDim.x + threadIdx.x;
    if (i < KCOMP) g_S0[i] = 0.f;
    if (i < KCOMP * DDIM) { g_S1[i] = 0.f; g_S2[i] = 0.f; }
}

// x -> fp16 (8 elements per thread)
__global__ void __launch_bounds__(256) xtoh(const float* __restrict__ x) {
    size_t i = ((size_t)blockIdx.x * 256 + threadIdx.x) * 8;
    float4 a = *(const float4*)(x + i);
    float4 b = *(const float4*)(x + i + 4);
    __half2 h[4];
    h[0] = __floats2half2_rn(a.x, a.y);
    h[1] = __floats2half2_rn(a.z, a.w);
    h[2] = __floats2half2_rn(b.x, b.y);
    h[3] = __floats2half2_rn(b.z, b.w);
    *(uint4*)(g_xh + i) = *(uint4*)h;
}

// Transpose W [K][Nd] -> Wt [Nd][K] fp16
__global__ void transpose_h(const float* __restrict__ W, __half* __restrict__ Wt,
                            int K, int Nd)
{
    __shared__ float t[32][33];
    int n0 = blockIdx.x * 32, k0 = blockIdx.y * 32;
    int x = threadIdx.x, y = threadIdx.y;
    for (int i = y; i < 32; i += 8) {
        int k = k0 + i, n = n0 + x;
        t[i][x] = (k < K && n < Nd) ? W[(size_t)k * Nd + n] : 0.f;
    }
    __syncthreads();
    for (int i = y; i < 32; i += 8) {
        int n = n0 + i, k = k0 + x;
        if (n < Nd && k < K)
            Wt[(size_t)n * K + k] = __float2half_rn(t[x][i]);
    }
}

// ---------------------------------------------------------------------------
// fp16 GEMM + bias + softplus, fp16 in/out
// BM=128, BN=128, BK=32, 256 thr, 8 warps (4m x 2n)
// ---------------------------------------------------------------------------
#define AST  40
#define ASTB 80
#define STGH (128 * AST)
#define STGB (STGH * 2)
#define GEMM_SMEM (4 * STGB)

__global__ void __launch_bounds__(256)
gemm_h(const __half* __restrict__ A, const __half* __restrict__ Bt,
       const float* __restrict__ bias, __half* __restrict__ C,
       int M, int Nd)
{
    extern __shared__ char smraw[];
    __half* Asm = (__half*)smraw;
    __half* Bsm = (__half*)(smraw + 2 * STGB);
    const uint32_t sb = smem_u32(smraw);

    const int tid = threadIdx.x, lane = tid & 31, warp = tid >> 5;
    const int wm = warp >> 1, wn = warp & 1;
    const int m0 = blockIdx.y * 128, n0 = blockIdx.x * 128;

    float acc[2][8][4];
#pragma unroll
    for (int i = 0; i < 2; i++)
#pragma unroll
        for (int j = 0; j < 8; j++)
#pragma unroll
            for (int q = 0; q < 4; q++) acc[i][j][q] = 0.f;

    const int rh[2] = { tid >> 2, (tid + 256) >> 2 };
    const int c8 = (tid & 3) * 8;

#pragma unroll
    for (int q = 0; q < 2; q++) {
        int r = rh[q];
        uint4 va = (m0 + r < M) ? *(const uint4*)(A + (size_t)(m0 + r) * 512 + c8)
                                : make_uint4(0, 0, 0, 0);
        *(uint4*)(Asm + r * AST + c8) = va;
        *(uint4*)(Bsm + r * AST + c8) = *(const uint4*)(Bt + (size_t)(n0 + r) * 512 + c8);
    }
    __syncthreads();

    const uint32_t aoff = sb + (wm * 32 + (lane & 15)) * ASTB + (lane >> 4) * 16;
    const uint32_t boff = sb + 2 * STGB
                        + (wn * 64 + (lane & 7) + ((lane >> 4) << 3)) * ASTB
                        + ((lane >> 3) & 1) * 16;

    for (int c = 0; c < 16; c++) {
        const int s = c & 1;
        uint4 pa[2], pb[2];
        if (c < 15) {
            int k0 = (c + 1) * 32;
#pragma unroll
            for (int q = 0; q < 2; q++) {
                int r = rh[q];
                pa[q] = (m0 + r < M) ? *(const uint4*)(A + (size_t)(m0 + r) * 512 + k0 + c8)
                                     : make_uint4(0, 0, 0, 0);
                pb[q] = *(const uint4*)(Bt + (size_t)(n0 + r) * 512 + k0 + c8);
            }
        }

        const uint32_t ab = aoff + s * STGB;
        const uint32_t bb = boff + s * STGB;
#pragma unroll
        for (int ks = 0; ks < 2; ks++) {
            uint32_t a0[4], a1[4];
            ldmx4(a0, ab + ks * 32);
            ldmx4(a1, ab + ks * 32 + 16 * ASTB);
#pragma unroll
            for (int p = 0; p < 4; p++) {
                uint32_t br[4];
                ldmx4(br, bb + ks * 32 + p * 16 * ASTB);
                mma_f16(acc[0][2 * p],     a0, br);
                mma_f16(acc[0][2 * p + 1], a0, br + 2);
                mma_f16(acc[1][2 * p],     a1, br);
                mma_f16(acc[1][2 * p + 1], a1, br + 2);
            }
        }

        if (c < 15) {
            __half* Ad = Asm + (s ^ 1) * STGH;
            __half* Bd = Bsm + (s ^ 1) * STGH;
#pragma unroll
            for (int q = 0; q < 2; q++) {
                *(uint4*)(Ad + rh[q] * AST + c8) = pa[q];
                *(uint4*)(Bd + rh[q] * AST + c8) = pb[q];
            }
            __syncthreads();
        }
    }

    const int gid = lane >> 2, tig = lane & 3;
#pragma unroll
    for (int i = 0; i < 2; i++) {
        int r = m0 + wm * 32 + i * 16 + gid;
#pragma unroll
        for (int j = 0; j < 8; j++) {
            int col = n0 + wn * 64 + j * 8 + 2 * tig;
            float b0 = __ldg(bias + col), b1 = __ldg(bias + col + 1);
            if (r < M)
                *(__half2*)(C + (size_t)r * Nd + col) =
                    __floats2half2_rn(softplusf(acc[i][j][0] + b0),
                                      softplusf(acc[i][j][1] + b1));
            if (r + 8 < M)
                *(__half2*)(C + (size_t)(r + 8) * Nd + col) =
                    __floats2half2_rn(softplusf(acc[i][j][2] + b0),
                                      softplusf(acc[i][j][3] + b1));
        }
    }
}

// ---------------------------------------------------------------------------
// attn: att = softmax(h2 @ W3t^T + b3) via MMA; writes fp16 att + fp32 S0
// block: 128 thr / 4 warps, 64 rows; K=256 in 16 k16 chunks
// ---------------------------------------------------------------------------
#define AT_ST 264
#define AT_H2B (64 * AT_ST * 2)
#define ATT_SMEM (AT_H2B + 32 * AT_ST * 2)

__global__ void __launch_bounds__(128)
attn_mma(const float* __restrict__ b3)
{
    extern __shared__ char smraw[];
    __half* h2s = (__half*)smraw;                 // [64][264]
    __half* w3s = (__half*)(smraw + AT_H2B);      // [32][264]
    __shared__ float ssum[KCOMP];
    __shared__ float b3s[KCOMP];
    const uint32_t sb = smem_u32(smraw);

    const int tid = threadIdx.x, lane = tid & 31, w = tid >> 5;
    const int r0 = blockIdx.x * 64;

    if (tid < KCOMP) { ssum[tid] = 0.f; b3s[tid] = b3[tid]; }

#pragma unroll
    for (int q = 0; q < 8; q++) {
        int u = tid + q * 128;
        *(uint4*)(w3s + (u >> 5) * AT_ST + (u & 31) * 8) =
            *(const uint4*)(g_W3th + (u >> 5) * 256 + (u & 31) * 8);
    }
#pragma unroll
    for (int q = 0; q < 16; q++) {
        int u = tid + q * 128;
        int row = u >> 5, col = (u & 31) * 8;
        uint4 v = (r0 + row < NROWS)
            ? *(const uint4*)(g_h2h + (size_t)(r0 + row) * 256 + col)
            : make_uint4(0, 0, 0, 0);
        *(uint4*)(h2s + row * AT_ST + col) = v;
    }
    __syncthreads();

    float acc[4][4];
#pragma unroll
    for (int j = 0; j < 4; j++)
#pragma unroll
        for (int q = 0; q < 4; q++) acc[j][q] = 0.f;

    const uint32_t aoff = sb + (w * 16 + (lane & 15)) * (AT_ST * 2) + (lane >> 4) * 16;
    const uint32_t boff0 = sb + AT_H2B
                         + ((lane & 7) + ((lane >> 4) << 3)) * (AT_ST * 2)
                         + ((lane >> 3) & 1) * 16;
    const uint32_t boff1 = boff0 + 16 * (AT_ST * 2);

#pragma unroll
    for (int c = 0; c < 16; c++) {
        uint32_t a[4], b0[4], b1[4];
        ldmx4(a,  aoff  + c * 32);
        ldmx4(b0, boff0 + c * 32);
        ldmx4(b1, boff1 + c * 32);
        mma_f16(acc[0], a, b0);
        mma_f16(acc[1], a, b0 + 2);
        mma_f16(acc[2], a, b1);
        mma_f16(acc[3], a, b1 + 2);
    }

    // softmax: rows rowA (g) and rowB (g+8); 8 cols per row in this thread
    const int g = lane >> 2, t = lane & 3;
    const int rowA = r0 + w * 16 + g, rowB = rowA + 8;
    float vA[8], vB[8];
#pragma unroll
    for (int j = 0; j < 4; j++) {
        int col = 8 * j + 2 * t;
        vA[2 * j]     = acc[j][0] + b3s[col];
        vA[2 * j + 1] = acc[j][1] + b3s[col + 1];
        vB[2 * j]     = acc[j][2] + b3s[col];
        vB[2 * j + 1] = acc[j][3] + b3s[col + 1];
    }
    float mA = vA[0], mB = vB[0];
#pragma unroll
    for (int i = 1; i < 8; i++) { mA = fmaxf(mA, vA[i]); mB = fmaxf(mB, vB[i]); }
    mA = fmaxf(mA, __shfl_xor_sync(0xffffffffu, mA, 1));
    mA = fmaxf(mA, __shfl_xor_sync(0xffffffffu, mA, 2));
    mB = fmaxf(mB, __shfl_xor_sync(0xffffffffu, mB, 1));
    mB = fmaxf(mB, __shfl_xor_sync(0xffffffffu, mB, 2));
    float sA = 0.f, sB = 0.f;
#pragma unroll
    for (int i = 0; i < 8; i++) {
        vA[i] = expf(vA[i] - mA); sA += vA[i];
        vB[i] = expf(vB[i] - mB); sB += vB[i];
    }
    sA += __shfl_xor_sync(0xffffffffu, sA, 1);
    sA += __shfl_xor_sync(0xffffffffu, sA, 2);
    sB += __shfl_xor_sync(0xffffffffu, sB, 1);
    sB += __shfl_xor_sync(0xffffffffu, sB, 2);
    const float rA = 1.f / sA, rB = 1.f / sB;

    if (rowA < NROWS) {
#pragma unroll
        for (int j = 0; j < 4; j++) {
            int col = 8 * j + 2 * t;
            float p0 = vA[2 * j] * rA, p1 = vA[2 * j + 1] * rA;
            *(__half2*)(g_atth + (size_t)rowA * KCOMP + col) = __floats2half2_rn(p0, p1);
            atomicAdd(&ssum[col], p0);
            atomicAdd(&ssum[col + 1], p1);
        }
    }
    if (rowB < NROWS) {
#pragma unroll
        for (int j = 0; j < 4; j++) {
            int col = 8 * j + 2 * t;
            float p0 = vB[2 * j] * rB, p1 = vB[2 * j + 1] * rB;
            *(__half2*)(g_atth + (size_t)rowB * KCOMP + col) = __floats2half2_rn(p0, p1);
            atomicAdd(&ssum[col], p0);
            atomicAdd(&ssum[col + 1], p1);
        }
    }
    __syncthreads();
    if (tid < KCOMP) atomicAdd(&g_S0[tid], ssum[tid]);
}

// ---------------------------------------------------------------------------
// stats via MMA: S1[k,d] += att^T x ; S2[k,d] += att^T x^2 (x^2 by frag squaring)
// grid (49 n-chunks, 8 d-tiles), 128 thr / 4 warps (d 16 each), chunk = 2048 rows
// ---------------------------------------------------------------------------
#define SCH 2048
#define SA_ST 40
#define SX_ST 72

__global__ void __launch_bounds__(128)
stats_mma()
{
    __shared__ __half attS[2][64][SA_ST];
    __shared__ __half xS[2][64][SX_ST];
    const uint32_t sbA = smem_u32(&attS[0][0][0]);
    const uint32_t sbX = smem_u32(&xS[0][0][0]);

    const int tid = threadIdx.x, lane = tid & 31, w = tid >> 5;
    const int n0 = blockIdx.x * SCH;
    const int d0 = blockIdx.y * 64;

    float s1[2][2][4], s2[2][2][4];
#pragma unroll
    for (int i = 0; i < 2; i++)
#pragma unroll
        for (int j = 0; j < 2; j++)
#pragma unroll
            for (int q = 0; q < 4; q++) { s1[i][j][q] = 0.f; s2[i][j][q] = 0.f; }

    // stage-0 load
#pragma unroll
    for (int q = 0; q < 2; q++) {
        int u = tid + q * 128, row = u >> 2, col = (u & 3) * 8;
        uint4 v = (n0 + row < NROWS)
            ? *(const uint4*)(g_atth + (size_t)(n0 + row) * KCOMP + col)
            : make_uint4(0, 0, 0, 0);
        *(uint4*)(&attS[0][row][col]) = v;
    }
#pragma unroll
    for (int q = 0; q < 4; q++) {
        int u = tid + q * 128, row = u >> 3, col = (u & 7) * 8;
        uint4 v = (n0 + row < NROWS)
            ? *(const uint4*)(g_xh + (size_t)(n0 + row) * DDIM + d0 + col)
            : make_uint4(0, 0, 0, 0);
        *(uint4*)(&xS[0][row][col]) = v;
    }
    __syncthreads();

    const uint32_t aoff = sbA + ((lane & 7) + ((lane >> 4) << 3)) * (SA_ST * 2)
                        + ((lane >> 3) & 1) * 16;
    const uint32_t boff = sbX + (lane & 15) * (SX_ST * 2) + (lane >> 4) * 16 + w * 32;

    for (int step = 0; step < SCH / 64; step++) {
        const int s = step & 1;
        uint4 pa[2], px[4];
        if (step < SCH / 64 - 1) {
            int nb = n0 + (step + 1) * 64;
#pragma unroll
            for (int q = 0; q < 2; q++) {
                int u = tid + q * 128, row = u >> 2, col = (u & 3) * 8;
                pa[q] = (nb + row < NROWS)
                    ? *(const uint4*)(g_atth + (size_t)(nb + row) * KCOMP + col)
                    : make_uint4(0, 0, 0, 0);
            }
#pragma unroll
            for (int q = 0; q < 4; q++) {
                int u = tid + q * 128, row = u >> 3, col = (u & 7) * 8;
                px[q] = (nb + row < NROWS)
                    ? *(const uint4*)(g_xh + (size_t)(nb + row) * DDIM + d0 + col)
                    : make_uint4(0, 0, 0, 0);
            }
        }

        const uint32_t as = aoff + s * (64 * SA_ST * 2);
        const uint32_t bs = boff + s * (64 * SX_ST * 2);
#pragma unroll
        for (int t16 = 0; t16 < 4; t16++) {
            uint32_t a0[4], a1[4], b[4], b2[4];
            ldmx4t(a0, as + t16 * (16 * SA_ST * 2));
            ldmx4t(a1, as + t16 * (16 * SA_ST * 2) + 32);
            ldmx4t(b,  bs + t16 * (16 * SX_ST * 2));
#pragma unroll
            for (int i = 0; i < 4; i++) b2[i] = sqh2(b[i]);
            mma_f16(s1[0][0], a0, b);
            mma_f16(s1[0][1], a0, b + 2);
            mma_f16(s1[1][0], a1, b);
            mma_f16(s1[1][1], a1, b + 2);
            mma_f16(s2[0][0], a0, b2);
            mma_f16(s2[0][1], a0, b2 + 2);
            mma_f16(s2[1][0], a1, b2);
            mma_f16(s2[1][1], a1, b2 + 2);
        }

        if (step < SCH / 64 - 1) {
#pragma unroll
            for (int q = 0; q < 2; q++) {
                int u = tid + q * 128;
                *(uint4*)(&attS[s ^ 1][u >> 2][(u & 3) * 8]) = pa[q];
            }
#pragma unroll
            for (int q = 0; q < 4; q++) {
                int u = tid + q * 128;
                *(uint4*)(&xS[s ^ 1][u >> 3][(u & 7) * 8]) = px[q];
            }
            __syncthreads();
        }
    }

    const int g = lane >> 2, t = lane & 3;
#pragma unroll
    for (int i = 0; i < 2; i++) {
#pragma unroll
        for (int j = 0; j < 2; j++) {
            int kc = i * 16 + g;
            int d  = d0 + w * 16 + j * 8 + 2 * t;
            atomicAdd(&g_S1[kc * DDIM + d],           s1[i][j][0]);
            atomicAdd(&g_S1[kc * DDIM + d + 1],       s1[i][j][1]);
            atomicAdd(&g_S1[(kc + 8) * DDIM + d],     s1[i][j][2]);
            atomicAdd(&g_S1[(kc + 8) * DDIM + d + 1], s1[i][j][3]);
            atomicAdd(&g_S2[kc * DDIM + d],           s2[i][j][0]);
            atomicAdd(&g_S2[kc * DDIM + d + 1],       s2[i][j][1]);
            atomicAdd(&g_S2[(kc + 8) * DDIM + d],     s2[i][j][2]);
            atomicAdd(&g_S2[(kc + 8) * DDIM + d + 1], s2[i][j][3]);
        }
    }
}

// ---------------------------------------------------------------------------
// Finalize params; vars output + Bm/Bv/Ck
// ---------------------------------------------------------------------------
__global__ void __launch_bounds__(256)
finalize_kernel(float* __restrict__ out_vars)
{
    const int k = blockIdx.x;
    const int t = threadIdx.x;
    const float inv_s0 = 1.0f / g_S0[k];

    float csum = 0.f;
    for (int d = t; d < DDIM; d += 256) {
        float mean = g_S1[k * DDIM + d] * inv_s0;
        float ex2  = g_S2[k * DDIM + d] * inv_s0;
        float var  = ex2 - mean * mean;
        float iv   = 1.0f / var;
        float miv  = mean * iv;
        out_vars[k * DDIM + d] = var;
        g_Bm[k * DDIM + d] = __float2half_rn(miv);
        g_Bv[k * DDIM + d] = __float2half_rn(-0.5f * iv);
        csum += mean * miv + logf(var);
    }

    __shared__ float red[256];
    red[t] = csum;
    __syncthreads();
    if (t < 128) red[t] += red[t + 128];
    __syncthreads();
    if (t < 64) red[t] += red[t + 64];
    __syncthreads();
    if (t < 32) {
        float v = red[t] + red[t + 32];
#pragma unroll
        for (int o = 16; o > 0; o >>= 1) v += __shfl_xor_sync(0xffffffffu, v, o);
        if (t == 0)
            g_Ck[k] = -0.5f * v - (float)DDIM * 0.9189385332046727f;
    }
}

// ---------------------------------------------------------------------------
// GMM output: out[n,k] = x@Bm^T + x^2@Bv^T + Ck (x^2 via A-fragment squaring)
// ---------------------------------------------------------------------------
__global__ void __launch_bounds__(256)
gmm_mma(float* __restrict__ out)
{
    __shared__ __half Ax[2][128][AST];
    __shared__ __half Bms[2][32][AST];
    __shared__ __half Bvs[2][32][AST];
    __shared__ float sck[KCOMP];
    const uint32_t sbA = smem_u32(&Ax[0][0][0]);
    const uint32_t sbM = smem_u32(&Bms[0][0][0]);
    const uint32_t sbV = smem_u32(&Bvs[0][0][0]);

    const int tid = threadIdx.x, lane = tid & 31, w = tid >> 5;
    const int m0 = blockIdx.x * 128;

    if (tid < KCOMP) sck[tid] = g_Ck[tid];

    float acc[4][4];
#pragma unroll
    for (int j = 0; j < 4; j++)
#pragma unroll
        for (int q = 0; q < 4; q++) acc[j][q] = 0.f;

    const int arow[2] = { tid >> 2, (tid + 256) >> 2 };
    const int ac8 = (tid & 3) * 8;
    const int bu = tid & 127;
    const int brow = bu >> 2, bc8 = (bu & 3) * 8;
    const __half* Bg = (tid < 128) ? g_Bm : g_Bv;

    // stage 0
#pragma unroll
    for (int q = 0; q < 2; q++) {
        int r = arow[q];
        uint4 v = (m0 + r < NROWS) ? *(const uint4*)(g_xh + (size_t)(m0 + r) * DDIM + ac8)
                                   : make_uint4(0, 0, 0, 0);
        *(uint4*)(&Ax[0][r][ac8]) = v;
    }
    {
        uint4 v = *(const uint4*)(Bg + brow * DDIM + bc8);
        if (tid < 128) *(uint4*)(&Bms[0][brow][bc8]) = v;
        else           *(uint4*)(&Bvs[0][brow][bc8]) = v;
    }
    __syncthreads();

    const uint32_t aoff = sbA + (w * 16 + (lane & 15)) * ASTB + (lane >> 4) * 16;
    const uint32_t moff = sbM + ((lane & 7) + ((lane >> 4) << 3)) * ASTB + ((lane >> 3) & 1) * 16;
    const uint32_t voff = sbV + ((lane & 7) + ((lane >> 4) << 3)) * ASTB + ((lane >> 3) & 1) * 16;

    for (int c = 0; c < 16; c++) {
        const int s = c & 1;
        uint4 pa[2], pbb;
        if (c < 15) {
            int k0 = (c + 1) * 32;
#pragma unroll
            for (int q = 0; q < 2; q++) {
                int r = arow[q];
                pa[q] = (m0 + r < NROWS) ? *(const uint4*)(g_xh + (size_t)(m0 + r) * DDIM + k0 + ac8)
                                         : make_uint4(0, 0, 0, 0);
            }
            pbb = *(const uint4*)(Bg + brow * DDIM + k0 + bc8);
        }

        const uint32_t as = aoff + s * (128 * ASTB);
        const uint32_t ms = moff + s * (32 * ASTB);
        const uint32_t vs = voff + s * (32 * ASTB);
#pragma unroll
        for (int ks = 0; ks < 2; ks++) {
            uint32_t a[4], a2[4];
            ldmx4(a, as + ks * 32);
#pragma unroll
            for (int i = 0; i < 4; i++) a2[i] = sqh2(a[i]);
#pragma unroll
            for (int p = 0; p < 2; p++) {
                uint32_t bm[4], bv[4];
                ldmx4(bm, ms + ks * 32 + p * 16 * ASTB);
                ldmx4(bv, vs + ks * 32 + p * 16 * ASTB);
                mma_f16(acc[2 * p],     a,  bm);
                mma_f16(acc[2 * p + 1], a,  bm + 2);
                mma_f16(acc[2 * p],     a2, bv);
                mma_f16(acc[2 * p + 1], a2, bv + 2);
            }
        }

        if (c < 15) {
#pragma unroll
            for (int q = 0; q < 2; q++)
                *(uint4*)(&Ax[s ^ 1][arow[q]][ac8]) = pa[q];
            if (tid < 128) *(uint4*)(&Bms[s ^ 1][brow][bc8]) = pbb;
            else           *(uint4*)(&Bvs[s ^ 1][brow][bc8]) = pbb;
            __syncthreads();
        }
    }

    const int g = lane >> 2, t = lane & 3;
    const int r0 = m0 + w * 16 + g;
#pragma unroll
    for (int j = 0; j < 4; j++) {
        int col = j * 8 + 2 * t;
        float ck0 = sck[col], ck1 = sck[col + 1];
        if (r0 < NROWS) {
            float2 o = { acc[j][0] + ck0, acc[j][1] + ck1 };
            *(float2*)(out + (size_t)r0 * KCOMP + col) = o;
        }
        if (r0 + 8 < NROWS) {
            float2 o = { acc[j][2] + ck0, acc[j][3] + ck1 };
            *(float2*)(out + (size_t)(r0 + 8) * KCOMP + col) = o;
        }
    }
}

// ---------------------------------------------------------------------------
// Launch
// ---------------------------------------------------------------------------
extern "C" void kernel_launch(void* const* d_in, const int* in_sizes, int n_in,
                              void* d_out, int out_size)
{
    const float* x  = (const float*)d_in[0];
    const float* W1 = (const float*)d_in[1];
    const float* b1 = (const float*)d_in[2];
    const float* W2 = (const float*)d_in[3];
    const float* b2 = (const float*)d_in[4];
    const float* W3 = (const float*)d_in[5];
    const float* b3 = (const float*)d_in[6];
    float* out = (float*)d_out;

    __half *xhp = nullptr, *h1p = nullptr, *h2p = nullptr;
    __half *w1tp = nullptr, *w2tp = nullptr, *w3tp = nullptr;
    cudaGetSymbolAddress((void**)&xhp, g_xh);
    cudaGetSymbolAddress((void**)&h1p, g_h1h);
    cudaGetSymbolAddress((void**)&h2p, g_h2h);
    cudaGetSymbolAddress((void**)&w1tp, g_W1th);
    cudaGetSymbolAddress((void**)&w2tp, g_W2th);
    cudaGetSymbolAddress((void**)&w3tp, g_W3th);

    cudaFuncSetAttribute(gemm_h,   cudaFuncAttributeMaxDynamicSharedMemorySize, GEMM_SMEM);
    cudaFuncSetAttribute(attn_mma, cudaFuncAttributeMaxDynamicSharedMemorySize, ATT_SMEM);

    zero_kernel<<<64, 256>>>();
    xtoh<<<(NROWS * DDIM) / (256 * 8), 256>>>(x);
    transpose_h<<<dim3(H1DIM / 32, DDIM / 32), dim3(32, 8)>>>(W1, w1tp, DDIM, H1DIM);
    transpose_h<<<dim3(H2DIM / 32, H1DIM / 32), dim3(32, 8)>>>(W2, w2tp, H1DIM, H2DIM);
    transpose_h<<<dim3(1, H2DIM / 32), dim3(32, 8)>>>(W3, w3tp, H2DIM, KCOMP);

    const int mtiles = (NROWS + 127) / 128;  // 782

    // 1) h1 = softplus(x @ W1 + b1)
    gemm_h<<<dim3(H1DIM / 128, mtiles), 256, GEMM_SMEM>>>(xhp, w1tp, b1, h1p, NROWS, H1DIM);

    // 2) h2 = softplus(h1 @ W2 + b2)
    gemm_h<<<dim3(H2DIM / 128, mtiles), 256, GEMM_SMEM>>>(h1p, w2tp, b2, h2p, NROWS, H2DIM);

    // 3) att = softmax(h2 @ W3 + b3) [MMA] -> fp16 att + S0
    attn_mma<<<(NROWS + 63) / 64, 128, ATT_SMEM>>>(b3);

    // 4) weighted stats via MMA
    stats_mma<<<dim3((NROWS + SCH - 1) / SCH, DDIM / 64), 128>>>();

    // 5) finalize: vars output + Bm/Bv/Ck
    finalize_kernel<<<KCOMP, 256>>>(out + (size_t)NROWS * KCOMP);

    // 6) GMM log-likelihood via MMA
    gmm_mma<<<mtiles, 256>>>(out);
}